// round 15
// baseline (speedup 1.0000x reference)
#include <cuda_runtime.h>
#include <math.h>

// Problem constants
#define Bb 256
#define Tt 512
#define Ii 64
#define Hh 128
#define GH 512          // 4*H
#define NB 4            // batch samples per recurrence CTA

// lstm_rec weight smem chunk layout (R10/R12, proven): chunk = (row, kh) holds
// 24 fp32 (cols [32kh,32kh+24)); chunks grouped by 8 with strides 28,...,28,24
// -> every 8-lane phase hits distinct bank quads. 2048 chunks, 256 groups.
#define CHW 28
#define GRPW 220
#define WWORDS (256 * GRPW)        // 56320 words = 225280 B
#define HSW 544                    // hs buffer words (128 ks * 4 + 8-word gap / 32 ks)

typedef unsigned long long ull;

__device__ __forceinline__ int wchunk(int idx) {
    return (idx >> 3) * GRPW + (idx & 7) * CHW;
}

// ---------------- scratch (device globals; no cudaMalloc allowed) ----------
__device__ float g_xg[2 * Bb * Tt * GH];     // [dir][b][t][4H]  (natural order)
__device__ float g_h0[Bb * Tt * 2 * Hh];     // layer0 output [b][t][2H]
__device__ float g_h1[Bb * Tt * 2 * Hh];     // layer1 output (only t=T-1 valid)

// ---------------- f32x2 helpers (packed fp32 FMA, sm_100+) -----------------
__device__ __forceinline__ ull pk2(float x, float y) {
    ull r; asm("mov.b64 %0, {%1, %2};" : "=l"(r) : "f"(x), "f"(y)); return r;
}
__device__ __forceinline__ void fma2(ull& d, ull a, ull b) {
    asm("fma.rn.f32x2 %0, %1, %2, %0;" : "+l"(d) : "l"(a), "l"(b));
}
__device__ __forceinline__ ull add2(ull a, ull b) {
    ull r; asm("add.rn.f32x2 %0, %1, %2;" : "=l"(r) : "l"(a), "l"(b)); return r;
}
__device__ __forceinline__ void unpk2(ull v, float& x, float& y) {
    asm("mov.b64 {%0, %1}, %2;" : "=f"(x), "=f"(y) : "l"(v));
}
__device__ __forceinline__ float f4c(const float4 v, int i) {
    return i == 0 ? v.x : i == 1 ? v.y : i == 2 ? v.z : v.w;
}
// fast activations: __expf + MUFU.RCP; proven rel err ~3.5e-7 end-to-end
__device__ __forceinline__ float sigf(float x) {
    float e = __expf(-x);
    return __fdividef(1.0f, 1.0f + e);
}
__device__ __forceinline__ float tanhfast(float x) {
    float e = __expf(-2.0f * x);
    return __fdividef(1.0f - e, 1.0f + e);
}

// ---------------- xg GEMM v3: mov-free f32x2 inner loop ---------------------
// Y[dir][m][n] = X[m,:]·W[n,:] + bih[n]+bhh[n].
// CTA tile 128m x 128n, BK=16, 256 threads, thread tile 8x8 (4+4 split).
// X stored DUPLICATED in smem ([k][2m]=[k][2m+1]=x) so a 16B LDS yields the
// packed-dup operand {x,x} directly; W loaded as ulonglong2 (consecutive
// {w0,w1} IS the packed pair). Zero pack movs in the inner loop.
// Smem exactly 48KB static -> 2 CTAs/SM (reg cap 128).
__global__ void __launch_bounds__(256, 2) xg_gemm(
    const float* __restrict__ X0, int layer, int K,
    const float* __restrict__ W0, const float* __restrict__ W1,
    const float* __restrict__ bi0, const float* __restrict__ bh0,
    const float* __restrict__ bi1, const float* __restrict__ bh1)
{
    const int M = Bb * Tt;
    __shared__ float Xs[2][16][256];    // duplicated X: 32KB
    __shared__ float Ws[2][16][128];    // W: 16KB (total 48KB exactly)
    const float* X  = layer ? g_h0 : X0;
    const int dir   = blockIdx.z;
    const float* W  = dir ? W1 : W0;
    const float* bi = dir ? bi1 : bi0;
    const float* bh = dir ? bh1 : bh0;
    const int m0 = blockIdx.x * 128;
    const int n0 = blockIdx.y * 128;
    const int tid = threadIdx.x;
    const int tx = tid & 15, ty = tid >> 4;
    const int gr = tid & 127, qh = tid >> 7;   // global-load row, k-half

    const float* Xp = X + (size_t)(m0 + gr) * K + 8 * qh;
    const float* Wp = W + (size_t)(n0 + gr) * K + 8 * qh;

    float4 xr0 = *(const float4*)Xp, xr1 = *(const float4*)(Xp + 4);
    float4 wr0 = *(const float4*)Wp, wr1 = *(const float4*)(Wp + 4);
    const int kq = 8 * qh;
#define STX(buf, j, v) do { float2 _d; _d.x = _d.y = (v); \
    *(float2*)&Xs[buf][kq + (j)][2 * gr] = _d; } while (0)
    STX(0, 0, xr0.x); STX(0, 1, xr0.y); STX(0, 2, xr0.z); STX(0, 3, xr0.w);
    STX(0, 4, xr1.x); STX(0, 5, xr1.y); STX(0, 6, xr1.z); STX(0, 7, xr1.w);
    Ws[0][kq+0][gr]=wr0.x; Ws[0][kq+1][gr]=wr0.y; Ws[0][kq+2][gr]=wr0.z; Ws[0][kq+3][gr]=wr0.w;
    Ws[0][kq+4][gr]=wr1.x; Ws[0][kq+5][gr]=wr1.y; Ws[0][kq+6][gr]=wr1.z; Ws[0][kq+7][gr]=wr1.w;
    __syncthreads();

    ull acc[8][4];
#pragma unroll
    for (int i = 0; i < 8; i++)
#pragma unroll
        for (int j = 0; j < 4; j++) acc[i][j] = 0ull;

    const int NIT = K / 16;
    for (int it = 0; it < NIT; ++it) {
        const int cur = it & 1;
        if (it + 1 < NIT) {
            const float* xp = Xp + (it + 1) * 16;
            const float* wp = Wp + (it + 1) * 16;
            xr0 = *(const float4*)xp; xr1 = *(const float4*)(xp + 4);
            wr0 = *(const float4*)wp; wr1 = *(const float4*)(wp + 4);
        }
#pragma unroll
        for (int k = 0; k < 16; ++k) {
            // duplicated X: each .x/.y is already a packed {x,x} pair
            ulonglong2 xa0 = *(const ulonglong2*)&Xs[cur][k][8 * ty];        // m0,m1
            ulonglong2 xa1 = *(const ulonglong2*)&Xs[cur][k][8 * ty + 4];    // m2,m3
            ulonglong2 xb0 = *(const ulonglong2*)&Xs[cur][k][128 + 8 * ty];  // m4,m5
            ulonglong2 xb1 = *(const ulonglong2*)&Xs[cur][k][128 + 8 * ty + 4];
            // W pairs come packed straight from memory
            ulonglong2 wA = *(const ulonglong2*)&Ws[cur][k][tx * 4];
            ulonglong2 wB = *(const ulonglong2*)&Ws[cur][k][64 + tx * 4];
            fma2(acc[0][0], xa0.x, wA.x); fma2(acc[0][1], xa0.x, wA.y);
            fma2(acc[0][2], xa0.x, wB.x); fma2(acc[0][3], xa0.x, wB.y);
            fma2(acc[1][0], xa0.y, wA.x); fma2(acc[1][1], xa0.y, wA.y);
            fma2(acc[1][2], xa0.y, wB.x); fma2(acc[1][3], xa0.y, wB.y);
            fma2(acc[2][0], xa1.x, wA.x); fma2(acc[2][1], xa1.x, wA.y);
            fma2(acc[2][2], xa1.x, wB.x); fma2(acc[2][3], xa1.x, wB.y);
            fma2(acc[3][0], xa1.y, wA.x); fma2(acc[3][1], xa1.y, wA.y);
            fma2(acc[3][2], xa1.y, wB.x); fma2(acc[3][3], xa1.y, wB.y);
            fma2(acc[4][0], xb0.x, wA.x); fma2(acc[4][1], xb0.x, wA.y);
            fma2(acc[4][2], xb0.x, wB.x); fma2(acc[4][3], xb0.x, wB.y);
            fma2(acc[5][0], xb0.y, wA.x); fma2(acc[5][1], xb0.y, wA.y);
            fma2(acc[5][2], xb0.y, wB.x); fma2(acc[5][3], xb0.y, wB.y);
            fma2(acc[6][0], xb1.x, wA.x); fma2(acc[6][1], xb1.x, wA.y);
            fma2(acc[6][2], xb1.x, wB.x); fma2(acc[6][3], xb1.x, wB.y);
            fma2(acc[7][0], xb1.y, wA.x); fma2(acc[7][1], xb1.y, wA.y);
            fma2(acc[7][2], xb1.y, wB.x); fma2(acc[7][3], xb1.y, wB.y);
        }
        if (it + 1 < NIT) {
            const int nxt = cur ^ 1;
            STX(nxt, 0, xr0.x); STX(nxt, 1, xr0.y); STX(nxt, 2, xr0.z); STX(nxt, 3, xr0.w);
            STX(nxt, 4, xr1.x); STX(nxt, 5, xr1.y); STX(nxt, 6, xr1.z); STX(nxt, 7, xr1.w);
            Ws[nxt][kq+0][gr]=wr0.x; Ws[nxt][kq+1][gr]=wr0.y; Ws[nxt][kq+2][gr]=wr0.z; Ws[nxt][kq+3][gr]=wr0.w;
            Ws[nxt][kq+4][gr]=wr1.x; Ws[nxt][kq+5][gr]=wr1.y; Ws[nxt][kq+6][gr]=wr1.z; Ws[nxt][kq+7][gr]=wr1.w;
        }
        __syncthreads();
    }
#undef STX

    const int na = n0 + tx * 4, nb = na + 64;
    float bsA[4], bsB[4];
#pragma unroll
    for (int j = 0; j < 4; j++) {
        bsA[j] = bi[na + j] + bh[na + j];
        bsB[j] = bi[nb + j] + bh[nb + j];
    }
    float* base = g_xg + (size_t)dir * M * GH;
#pragma unroll
    for (int i = 0; i < 8; ++i) {
        const int m = m0 + (i < 4 ? ty * 4 + i : 64 + ty * 4 + (i - 4));
        float* y = base + (size_t)m * GH;
        float4 v;
        unpk2(acc[i][0], v.x, v.y); unpk2(acc[i][1], v.z, v.w);
        v.x += bsA[0]; v.y += bsA[1]; v.z += bsA[2]; v.w += bsA[3];
        *(float4*)(y + na) = v;
        unpk2(acc[i][2], v.x, v.y); unpk2(acc[i][3], v.z, v.w);
        v.x += bsB[0]; v.y += bsB[1]; v.z += bsB[2]; v.w += bsB[3];
        *(float4*)(y + nb) = v;
    }
}

// ---------------- LSTM recurrence (R12, proven best) -------------------------
// 512 threads. Thread (q = tid>>2, kh = tid&3) computes partial dots over
// k in [32kh, 32kh+32) for ALL 4 gate rows {q, q+128, q+256, q+384}, 4
// batches. Quad shuffle reduce-scatter over kh leaves thread with gates
// 0..3 for (batch kh, unit q). One barrier/step; hs ping-pongs.
__global__ void __launch_bounds__(512, 1) lstm_rec(
    int layer,
    const float* __restrict__ Wf, const float* __restrict__ Wr)
{
    extern __shared__ float sm[];
    float* sW  = sm;                       // WWORDS
    float* hsA = sm + WWORDS;              // HSW words
    float* hsB = hsA + HSW;

    const int dir = blockIdx.y;
    const int b0  = blockIdx.x * NB;
    const float* Whh = dir ? Wr : Wf;
    float* hout = layer ? g_h1 : g_h0;
    const float* xg = g_xg + (size_t)dir * Bb * Tt * GH;
    const int tid = threadIdx.x;
    const int q = tid >> 2, kh = tid & 3;

    // cooperative weight load: 2048 chunks x 6 float4
    for (int i = tid; i < 2048 * 6; i += 512) {
        const int ch = i / 6, fq = i - ch * 6;
        const int r = ch >> 2, kq = ch & 3;
        float4 v = *(const float4*)(Whh + (size_t)r * Hh + kq * 32 + fq * 4);
        *(float4*)(sW + wchunk(ch) + fq * 4) = v;
    }
    for (int i = tid; i < 2 * HSW; i += 512) hsA[i] = 0.f;

    // register weights: rows g*128+q, cols [32kh+24, 32kh+32)
    float4 wra[4], wrb[4];
#pragma unroll
    for (int g = 0; g < 4; ++g) {
        const float* src = Whh + (size_t)(g * Hh + q) * Hh + 32 * kh + 24;
        wra[g] = *(const float4*)src;
        wrb[g] = *(const float4*)(src + 4);
    }

    const float* wp = sW + wchunk(4 * q + kh);   // g offsets: +14080*g words
    const int hb = 136 * kh;
    const int mypair = kh >> 1, mybit = kh & 1;
    float c0 = 0.f;
    float* hp = hout + (size_t)(b0 + kh) * Tt * (2 * Hh) + dir * Hh + q;
    const float* xrow = xg + (size_t)(b0 + kh) * Tt * GH + q;
    __syncthreads();

    for (int s = 0; s < Tt; ++s) {
        const int t = dir ? (Tt - 1 - s) : s;
        const float* hcur = (s & 1) ? hsB : hsA;
        float* hnxt       = (s & 1) ? hsA : hsB;
        const float* xt = xrow + (size_t)t * GH;
        float xq0 = xt[0], xq1 = xt[128], xq2 = xt[256], xq3 = xt[384];

        ull A01[4] = {0, 0, 0, 0}, A23[4] = {0, 0, 0, 0};
        const float* hq = hcur + hb;
#pragma unroll
        for (int jf = 0; jf < 6; ++jf) {
            float4 w0 = *(const float4*)(wp + jf * 4);
            float4 w1 = *(const float4*)(wp + 14080 + jf * 4);
            float4 w2 = *(const float4*)(wp + 28160 + jf * 4);
            float4 w3 = *(const float4*)(wp + 42240 + jf * 4);
#pragma unroll
            for (int kk = 0; kk < 4; ++kk) {
                float4 hv = *(const float4*)(hq + (jf * 4 + kk) * 4);
                ull h01 = pk2(hv.x, hv.y), h23 = pk2(hv.z, hv.w);
                ull m0 = pk2(f4c(w0, kk), f4c(w0, kk));
                ull m1 = pk2(f4c(w1, kk), f4c(w1, kk));
                ull m2 = pk2(f4c(w2, kk), f4c(w2, kk));
                ull m3 = pk2(f4c(w3, kk), f4c(w3, kk));
                fma2(A01[0], m0, h01); fma2(A23[0], m0, h23);
                fma2(A01[1], m1, h01); fma2(A23[1], m1, h23);
                fma2(A01[2], m2, h01); fma2(A23[2], m2, h23);
                fma2(A01[3], m3, h01); fma2(A23[3], m3, h23);
            }
        }
#pragma unroll
        for (int jr = 0; jr < 8; ++jr) {
            float4 hv = *(const float4*)(hq + (24 + jr) * 4);
            ull h01 = pk2(hv.x, hv.y), h23 = pk2(hv.z, hv.w);
            float f0 = jr < 4 ? f4c(wra[0], jr) : f4c(wrb[0], jr - 4);
            float f1 = jr < 4 ? f4c(wra[1], jr) : f4c(wrb[1], jr - 4);
            float f2 = jr < 4 ? f4c(wra[2], jr) : f4c(wrb[2], jr - 4);
            float f3 = jr < 4 ? f4c(wra[3], jr) : f4c(wrb[3], jr - 4);
            ull m0 = pk2(f0, f0), m1 = pk2(f1, f1), m2 = pk2(f2, f2), m3 = pk2(f3, f3);
            fma2(A01[0], m0, h01); fma2(A23[0], m0, h23);
            fma2(A01[1], m1, h01); fma2(A23[1], m1, h23);
            fma2(A01[2], m2, h01); fma2(A23[2], m2, h23);
            fma2(A01[3], m3, h01); fma2(A23[3], m3, h23);
        }

        // quad reduce-scatter over kh: end with gates 0..3 for batch kh
        ull R[4];
#pragma unroll
        for (int g = 0; g < 4; ++g) {
            ull snd  = mypair ? A01[g] : A23[g];
            ull keep = mypair ? A23[g] : A01[g];
            ull rcv = __shfl_xor_sync(0xffffffffu, snd, 2);
            R[g] = add2(keep, rcv);
        }
#pragma unroll
        for (int g = 0; g < 4; ++g) {
            ull rcv = __shfl_xor_sync(0xffffffffu, R[g], 1);
            R[g] = add2(R[g], rcv);
        }
        float G0, G1, G2, G3;
        {
            float lo, hi;
            unpk2(R[0], lo, hi); G0 = mybit ? hi : lo;
            unpk2(R[1], lo, hi); G1 = mybit ? hi : lo;
            unpk2(R[2], lo, hi); G2 = mybit ? hi : lo;
            unpk2(R[3], lo, hi); G3 = mybit ? hi : lo;
        }
        G0 += xq0; G1 += xq1; G2 += xq2; G3 += xq3;

        // elementwise: (batch kh, unit q)
        c0 = sigf(G1) * c0 + sigf(G0) * tanhfast(G2);
        float h = sigf(G3) * tanhfast(c0);
        hnxt[4 * q + 8 * (q >> 5) + kh] = h;
        if (layer == 0 || t == Tt - 1)          // layer1: only t=T-1 consumed
            hp[(size_t)t * (2 * Hh)] = h;
        __syncthreads();
    }
}

// ---------------- FC head: out[b] = relu(last@fc1^T+b1) @ fc2^T + b2 -------
__global__ void __launch_bounds__(128) fc_head(
    const float* __restrict__ fc1w, const float* __restrict__ fc1b,
    const float* __restrict__ fc2w, const float* __restrict__ fc2b,
    float* __restrict__ out)
{
    __shared__ float last[2 * Hh];
    __shared__ float red[Hh];
    const int b = blockIdx.x, tid = threadIdx.x;
    const float* src = g_h1 + ((size_t)b * Tt + (Tt - 1)) * (2 * Hh);
    last[tid] = src[tid];
    last[tid + Hh] = src[tid + Hh];
    __syncthreads();
    float s = fc1b[tid];
    const float* wr = fc1w + tid * (2 * Hh);
#pragma unroll 8
    for (int k = 0; k < 2 * Hh; ++k) s += wr[k] * last[k];
    red[tid] = fmaxf(s, 0.f) * fc2w[tid];
    __syncthreads();
    for (int st = 64; st > 0; st >>= 1) {
        if (tid < st) red[tid] += red[tid + st];
        __syncthreads();
    }
    if (tid == 0) out[b] = red[0] + fc2b[0];
}

// ---------------- launch ---------------------------------------------------
extern "C" void kernel_launch(void* const* d_in, const int* in_sizes, int n_in,
                              void* d_out, int out_size)
{
    (void)in_sizes; (void)n_in; (void)out_size;
    const float* x     = (const float*)d_in[0];
    const float* Wih0  = (const float*)d_in[1];
    const float* Whh0  = (const float*)d_in[2];
    const float* bih0  = (const float*)d_in[3];
    const float* bhh0  = (const float*)d_in[4];
    const float* Wih0r = (const float*)d_in[5];
    const float* Whh0r = (const float*)d_in[6];
    const float* bih0r = (const float*)d_in[7];
    const float* bhh0r = (const float*)d_in[8];
    const float* Wih1  = (const float*)d_in[9];
    const float* Whh1  = (const float*)d_in[10];
    const float* bih1  = (const float*)d_in[11];
    const float* bhh1  = (const float*)d_in[12];
    const float* Wih1r = (const float*)d_in[13];
    const float* Whh1r = (const float*)d_in[14];
    const float* bih1r = (const float*)d_in[15];
    const float* bhh1r = (const float*)d_in[16];
    const float* fc1w  = (const float*)d_in[17];
    const float* fc1b  = (const float*)d_in[18];
    const float* fc2w  = (const float*)d_in[19];
    const float* fc2b  = (const float*)d_in[20];
    float* out = (float*)d_out;

    const int SMEMR = (WWORDS + 2 * HSW) * 4;   // 229,632 B <= 232,448 cap
    cudaFuncSetAttribute(lstm_rec, cudaFuncAttributeMaxDynamicSharedMemorySize, SMEMR);

    dim3 gg(Bb * Tt / 128, GH / 128, 2);
    dim3 gr(Bb / NB, 2);

    // layer 0
    xg_gemm<<<gg, 256>>>(x, 0, Ii, Wih0, Wih0r, bih0, bhh0, bih0r, bhh0r);
    lstm_rec<<<gr, 512, SMEMR>>>(0, Whh0, Whh0r);
    // layer 1 (input = g_h0, K = 256)
    xg_gemm<<<gg, 256>>>(x, 1, 2 * Hh, Wih1, Wih1r, bih1, bhh1, bih1r, bhh1r);
    lstm_rec<<<gr, 512, SMEMR>>>(1, Whh1, Whh1r);
    // head
    fc_head<<<Bb, Hh>>>(fc1w, fc1b, fc2w, fc2b, out);
}

// round 16
// speedup vs baseline: 1.0695x; 1.0695x over previous
#include <cuda_runtime.h>
#include <math.h>

// Problem constants
#define Bb 256
#define Tt 512
#define Ii 64
#define Hh 128
#define GH 512          // 4*H
#define NB 4            // batch samples per recurrence CTA

// lstm_rec weight smem chunk layout (R10/R12, proven): chunk = (row, kh) holds
// 24 fp32 (cols [32kh,32kh+24)); chunks grouped by 8 with strides 28,...,28,24
// -> every 8-lane phase hits distinct bank quads. 2048 chunks, 256 groups.
#define CHW 28
#define GRPW 220
#define WWORDS (256 * GRPW)        // 56320 words = 225280 B
#define HSW 544                    // hs buffer words (128 ks * 4 + 8-word gap / 32 ks)

typedef unsigned long long ull;

__device__ __forceinline__ int wchunk(int idx) {
    return (idx >> 3) * GRPW + (idx & 7) * CHW;
}

// ---------------- scratch (device globals; no cudaMalloc allowed) ----------
__device__ float g_xg[2 * Bb * Tt * GH];     // [dir][b][t][4H]  (natural order)
__device__ float g_h0[Bb * Tt * 2 * Hh];     // layer0 output [b][t][2H]
__device__ float g_h1[Bb * Tt * 2 * Hh];     // layer1 output (only t=T-1 valid)

// ---------------- f32x2 helpers (packed fp32 FMA, sm_100+) -----------------
__device__ __forceinline__ ull pk2(float x, float y) {
    ull r; asm("mov.b64 %0, {%1, %2};" : "=l"(r) : "f"(x), "f"(y)); return r;
}
__device__ __forceinline__ void fma2(ull& d, ull a, ull b) {
    asm("fma.rn.f32x2 %0, %1, %2, %0;" : "+l"(d) : "l"(a), "l"(b));
}
__device__ __forceinline__ ull add2(ull a, ull b) {
    ull r; asm("add.rn.f32x2 %0, %1, %2;" : "=l"(r) : "l"(a), "l"(b)); return r;
}
__device__ __forceinline__ void unpk2(ull v, float& x, float& y) {
    asm("mov.b64 {%0, %1}, %2;" : "=f"(x), "=f"(y) : "l"(v));
}
__device__ __forceinline__ float f4c(const float4 v, int i) {
    return i == 0 ? v.x : i == 1 ? v.y : i == 2 ? v.z : v.w;
}
// fast activations: __expf + MUFU.RCP; proven rel err ~3.5e-7 end-to-end
__device__ __forceinline__ float sigf(float x) {
    float e = __expf(-x);
    return __fdividef(1.0f, 1.0f + e);
}
__device__ __forceinline__ float tanhfast(float x) {
    float e = __expf(-2.0f * x);
    return __fdividef(1.0f - e, 1.0f + e);
}

// ---------------- xg GEMM: Y[dir][m][n] = X[m,:]·W[n,:] + bih[n]+bhh[n] ----
// R12 structure (proven): CTA tile 128m x 128n, BK=16, 256 threads, 8x8
// thread tile (4+4 split), double-buffered smem, float4 epilogue, 2 CTAs/SM.
// R16 tweak: W pairs loaded as ulonglong2 — {w0,w1} consecutive in smem IS
// the packed f32x2 operand, deleting 4 pack movs per k at zero traffic cost.
__global__ void __launch_bounds__(256, 2) xg_gemm(
    const float* __restrict__ X0, int layer, int K,
    const float* __restrict__ W0, const float* __restrict__ W1,
    const float* __restrict__ bi0, const float* __restrict__ bh0,
    const float* __restrict__ bi1, const float* __restrict__ bh1)
{
    const int M = Bb * Tt;
    __shared__ float Xs[2][16][132];
    __shared__ float Ws[2][16][132];
    const float* X  = layer ? g_h0 : X0;
    const int dir   = blockIdx.z;
    const float* W  = dir ? W1 : W0;
    const float* bi = dir ? bi1 : bi0;
    const float* bh = dir ? bh1 : bh0;
    const int m0 = blockIdx.x * 128;
    const int n0 = blockIdx.y * 128;
    const int tid = threadIdx.x;
    const int tx = tid & 15, ty = tid >> 4;
    const int gr = tid & 127, qh = tid >> 7;

    const float* Xp = X + (size_t)(m0 + gr) * K + 8 * qh;
    const float* Wp = W + (size_t)(n0 + gr) * K + 8 * qh;

    float4 xr0 = *(const float4*)Xp, xr1 = *(const float4*)(Xp + 4);
    float4 wr0 = *(const float4*)Wp, wr1 = *(const float4*)(Wp + 4);
    const int kq = 8 * qh;
    Xs[0][kq+0][gr]=xr0.x; Xs[0][kq+1][gr]=xr0.y; Xs[0][kq+2][gr]=xr0.z; Xs[0][kq+3][gr]=xr0.w;
    Xs[0][kq+4][gr]=xr1.x; Xs[0][kq+5][gr]=xr1.y; Xs[0][kq+6][gr]=xr1.z; Xs[0][kq+7][gr]=xr1.w;
    Ws[0][kq+0][gr]=wr0.x; Ws[0][kq+1][gr]=wr0.y; Ws[0][kq+2][gr]=wr0.z; Ws[0][kq+3][gr]=wr0.w;
    Ws[0][kq+4][gr]=wr1.x; Ws[0][kq+5][gr]=wr1.y; Ws[0][kq+6][gr]=wr1.z; Ws[0][kq+7][gr]=wr1.w;
    __syncthreads();

    ull acc[8][4];
#pragma unroll
    for (int i = 0; i < 8; i++)
#pragma unroll
        for (int j = 0; j < 4; j++) acc[i][j] = 0ull;

    const int NIT = K / 16;
    for (int it = 0; it < NIT; ++it) {
        const int cur = it & 1;
        if (it + 1 < NIT) {
            const float* xp = Xp + (it + 1) * 16;
            const float* wp = Wp + (it + 1) * 16;
            xr0 = *(const float4*)xp; xr1 = *(const float4*)(xp + 4);
            wr0 = *(const float4*)wp; wr1 = *(const float4*)(wp + 4);
        }
#pragma unroll
        for (int k = 0; k < 16; ++k) {
            float4 xa = *(const float4*)&Xs[cur][k][ty * 4];
            float4 xb = *(const float4*)&Xs[cur][k][64 + ty * 4];
            // W pairs come packed straight from smem (same LDS.128 as before)
            ulonglong2 wA = *(const ulonglong2*)&Ws[cur][k][tx * 4];
            ulonglong2 wB = *(const ulonglong2*)&Ws[cur][k][64 + tx * 4];
            ull p0 = wA.x, p1 = wA.y, p2 = wB.x, p3 = wB.y;
            ull a;
            a = pk2(xa.x, xa.x);
            fma2(acc[0][0],a,p0); fma2(acc[0][1],a,p1); fma2(acc[0][2],a,p2); fma2(acc[0][3],a,p3);
            a = pk2(xa.y, xa.y);
            fma2(acc[1][0],a,p0); fma2(acc[1][1],a,p1); fma2(acc[1][2],a,p2); fma2(acc[1][3],a,p3);
            a = pk2(xa.z, xa.z);
            fma2(acc[2][0],a,p0); fma2(acc[2][1],a,p1); fma2(acc[2][2],a,p2); fma2(acc[2][3],a,p3);
            a = pk2(xa.w, xa.w);
            fma2(acc[3][0],a,p0); fma2(acc[3][1],a,p1); fma2(acc[3][2],a,p2); fma2(acc[3][3],a,p3);
            a = pk2(xb.x, xb.x);
            fma2(acc[4][0],a,p0); fma2(acc[4][1],a,p1); fma2(acc[4][2],a,p2); fma2(acc[4][3],a,p3);
            a = pk2(xb.y, xb.y);
            fma2(acc[5][0],a,p0); fma2(acc[5][1],a,p1); fma2(acc[5][2],a,p2); fma2(acc[5][3],a,p3);
            a = pk2(xb.z, xb.z);
            fma2(acc[6][0],a,p0); fma2(acc[6][1],a,p1); fma2(acc[6][2],a,p2); fma2(acc[6][3],a,p3);
            a = pk2(xb.w, xb.w);
            fma2(acc[7][0],a,p0); fma2(acc[7][1],a,p1); fma2(acc[7][2],a,p2); fma2(acc[7][3],a,p3);
        }
        if (it + 1 < NIT) {
            const int nxt = cur ^ 1;
            Xs[nxt][kq+0][gr]=xr0.x; Xs[nxt][kq+1][gr]=xr0.y; Xs[nxt][kq+2][gr]=xr0.z; Xs[nxt][kq+3][gr]=xr0.w;
            Xs[nxt][kq+4][gr]=xr1.x; Xs[nxt][kq+5][gr]=xr1.y; Xs[nxt][kq+6][gr]=xr1.z; Xs[nxt][kq+7][gr]=xr1.w;
            Ws[nxt][kq+0][gr]=wr0.x; Ws[nxt][kq+1][gr]=wr0.y; Ws[nxt][kq+2][gr]=wr0.z; Ws[nxt][kq+3][gr]=wr0.w;
            Ws[nxt][kq+4][gr]=wr1.x; Ws[nxt][kq+5][gr]=wr1.y; Ws[nxt][kq+6][gr]=wr1.z; Ws[nxt][kq+7][gr]=wr1.w;
        }
        __syncthreads();
    }

    const int na = n0 + tx * 4, nb = na + 64;
    float bsA[4], bsB[4];
#pragma unroll
    for (int j = 0; j < 4; j++) {
        bsA[j] = bi[na + j] + bh[na + j];
        bsB[j] = bi[nb + j] + bh[nb + j];
    }
    float* base = g_xg + (size_t)dir * M * GH;
#pragma unroll
    for (int i = 0; i < 8; ++i) {
        const int m = m0 + (i < 4 ? ty * 4 + i : 64 + ty * 4 + (i - 4));
        float* y = base + (size_t)m * GH;
        float4 v;
        unpk2(acc[i][0], v.x, v.y); unpk2(acc[i][1], v.z, v.w);
        v.x += bsA[0]; v.y += bsA[1]; v.z += bsA[2]; v.w += bsA[3];
        *(float4*)(y + na) = v;
        unpk2(acc[i][2], v.x, v.y); unpk2(acc[i][3], v.z, v.w);
        v.x += bsB[0]; v.y += bsB[1]; v.z += bsB[2]; v.w += bsB[3];
        *(float4*)(y + nb) = v;
    }
}

// ---------------- LSTM recurrence (R12, proven best) -------------------------
// 512 threads. Thread (q = tid>>2, kh = tid&3) computes partial dots over
// k in [32kh, 32kh+32) for ALL 4 gate rows {q, q+128, q+256, q+384}, 4
// batches. Quad shuffle reduce-scatter over kh leaves thread with gates
// 0..3 for (batch kh, unit q). One barrier/step; hs ping-pongs.
__global__ void __launch_bounds__(512, 1) lstm_rec(
    int layer,
    const float* __restrict__ Wf, const float* __restrict__ Wr)
{
    extern __shared__ float sm[];
    float* sW  = sm;                       // WWORDS
    float* hsA = sm + WWORDS;              // HSW words
    float* hsB = hsA + HSW;

    const int dir = blockIdx.y;
    const int b0  = blockIdx.x * NB;
    const float* Whh = dir ? Wr : Wf;
    float* hout = layer ? g_h1 : g_h0;
    const float* xg = g_xg + (size_t)dir * Bb * Tt * GH;
    const int tid = threadIdx.x;
    const int q = tid >> 2, kh = tid & 3;

    // cooperative weight load: 2048 chunks x 6 float4
    for (int i = tid; i < 2048 * 6; i += 512) {
        const int ch = i / 6, fq = i - ch * 6;
        const int r = ch >> 2, kq = ch & 3;
        float4 v = *(const float4*)(Whh + (size_t)r * Hh + kq * 32 + fq * 4);
        *(float4*)(sW + wchunk(ch) + fq * 4) = v;
    }
    for (int i = tid; i < 2 * HSW; i += 512) hsA[i] = 0.f;

    // register weights: rows g*128+q, cols [32kh+24, 32kh+32)
    float4 wra[4], wrb[4];
#pragma unroll
    for (int g = 0; g < 4; ++g) {
        const float* src = Whh + (size_t)(g * Hh + q) * Hh + 32 * kh + 24;
        wra[g] = *(const float4*)src;
        wrb[g] = *(const float4*)(src + 4);
    }

    const float* wp = sW + wchunk(4 * q + kh);   // g offsets: +14080*g words
    const int hb = 136 * kh;
    const int mypair = kh >> 1, mybit = kh & 1;
    float c0 = 0.f;
    float* hp = hout + (size_t)(b0 + kh) * Tt * (2 * Hh) + dir * Hh + q;
    const float* xrow = xg + (size_t)(b0 + kh) * Tt * GH + q;
    __syncthreads();

    for (int s = 0; s < Tt; ++s) {
        const int t = dir ? (Tt - 1 - s) : s;
        const float* hcur = (s & 1) ? hsB : hsA;
        float* hnxt       = (s & 1) ? hsA : hsB;
        const float* xt = xrow + (size_t)t * GH;
        float xq0 = xt[0], xq1 = xt[128], xq2 = xt[256], xq3 = xt[384];

        ull A01[4] = {0, 0, 0, 0}, A23[4] = {0, 0, 0, 0};
        const float* hq = hcur + hb;
#pragma unroll
        for (int jf = 0; jf < 6; ++jf) {
            float4 w0 = *(const float4*)(wp + jf * 4);
            float4 w1 = *(const float4*)(wp + 14080 + jf * 4);
            float4 w2 = *(const float4*)(wp + 28160 + jf * 4);
            float4 w3 = *(const float4*)(wp + 42240 + jf * 4);
#pragma unroll
            for (int kk = 0; kk < 4; ++kk) {
                float4 hv = *(const float4*)(hq + (jf * 4 + kk) * 4);
                ull h01 = pk2(hv.x, hv.y), h23 = pk2(hv.z, hv.w);
                ull m0 = pk2(f4c(w0, kk), f4c(w0, kk));
                ull m1 = pk2(f4c(w1, kk), f4c(w1, kk));
                ull m2 = pk2(f4c(w2, kk), f4c(w2, kk));
                ull m3 = pk2(f4c(w3, kk), f4c(w3, kk));
                fma2(A01[0], m0, h01); fma2(A23[0], m0, h23);
                fma2(A01[1], m1, h01); fma2(A23[1], m1, h23);
                fma2(A01[2], m2, h01); fma2(A23[2], m2, h23);
                fma2(A01[3], m3, h01); fma2(A23[3], m3, h23);
            }
        }
#pragma unroll
        for (int jr = 0; jr < 8; ++jr) {
            float4 hv = *(const float4*)(hq + (24 + jr) * 4);
            ull h01 = pk2(hv.x, hv.y), h23 = pk2(hv.z, hv.w);
            float f0 = jr < 4 ? f4c(wra[0], jr) : f4c(wrb[0], jr - 4);
            float f1 = jr < 4 ? f4c(wra[1], jr) : f4c(wrb[1], jr - 4);
            float f2 = jr < 4 ? f4c(wra[2], jr) : f4c(wrb[2], jr - 4);
            float f3 = jr < 4 ? f4c(wra[3], jr) : f4c(wrb[3], jr - 4);
            ull m0 = pk2(f0, f0), m1 = pk2(f1, f1), m2 = pk2(f2, f2), m3 = pk2(f3, f3);
            fma2(A01[0], m0, h01); fma2(A23[0], m0, h23);
            fma2(A01[1], m1, h01); fma2(A23[1], m1, h23);
            fma2(A01[2], m2, h01); fma2(A23[2], m2, h23);
            fma2(A01[3], m3, h01); fma2(A23[3], m3, h23);
        }

        // quad reduce-scatter over kh: end with gates 0..3 for batch kh
        ull R[4];
#pragma unroll
        for (int g = 0; g < 4; ++g) {
            ull snd  = mypair ? A01[g] : A23[g];
            ull keep = mypair ? A23[g] : A01[g];
            ull rcv = __shfl_xor_sync(0xffffffffu, snd, 2);
            R[g] = add2(keep, rcv);
        }
#pragma unroll
        for (int g = 0; g < 4; ++g) {
            ull rcv = __shfl_xor_sync(0xffffffffu, R[g], 1);
            R[g] = add2(R[g], rcv);
        }
        float G0, G1, G2, G3;
        {
            float lo, hi;
            unpk2(R[0], lo, hi); G0 = mybit ? hi : lo;
            unpk2(R[1], lo, hi); G1 = mybit ? hi : lo;
            unpk2(R[2], lo, hi); G2 = mybit ? hi : lo;
            unpk2(R[3], lo, hi); G3 = mybit ? hi : lo;
        }
        G0 += xq0; G1 += xq1; G2 += xq2; G3 += xq3;

        // elementwise: (batch kh, unit q)
        c0 = sigf(G1) * c0 + sigf(G0) * tanhfast(G2);
        float h = sigf(G3) * tanhfast(c0);
        hnxt[4 * q + 8 * (q >> 5) + kh] = h;
        if (layer == 0 || t == Tt - 1)          // layer1: only t=T-1 consumed
            hp[(size_t)t * (2 * Hh)] = h;
        __syncthreads();
    }
}

// ---------------- FC head: out[b] = relu(last@fc1^T+b1) @ fc2^T + b2 -------
__global__ void __launch_bounds__(128) fc_head(
    const float* __restrict__ fc1w, const float* __restrict__ fc1b,
    const float* __restrict__ fc2w, const float* __restrict__ fc2b,
    float* __restrict__ out)
{
    __shared__ float last[2 * Hh];
    __shared__ float red[Hh];
    const int b = blockIdx.x, tid = threadIdx.x;
    const float* src = g_h1 + ((size_t)b * Tt + (Tt - 1)) * (2 * Hh);
    last[tid] = src[tid];
    last[tid + Hh] = src[tid + Hh];
    __syncthreads();
    float s = fc1b[tid];
    const float* wr = fc1w + tid * (2 * Hh);
#pragma unroll 8
    for (int k = 0; k < 2 * Hh; ++k) s += wr[k] * last[k];
    red[tid] = fmaxf(s, 0.f) * fc2w[tid];
    __syncthreads();
    for (int st = 64; st > 0; st >>= 1) {
        if (tid < st) red[tid] += red[tid + st];
        __syncthreads();
    }
    if (tid == 0) out[b] = red[0] + fc2b[0];
}

// ---------------- launch ---------------------------------------------------
extern "C" void kernel_launch(void* const* d_in, const int* in_sizes, int n_in,
                              void* d_out, int out_size)
{
    (void)in_sizes; (void)n_in; (void)out_size;
    const float* x     = (const float*)d_in[0];
    const float* Wih0  = (const float*)d_in[1];
    const float* Whh0  = (const float*)d_in[2];
    const float* bih0  = (const float*)d_in[3];
    const float* bhh0  = (const float*)d_in[4];
    const float* Wih0r = (const float*)d_in[5];
    const float* Whh0r = (const float*)d_in[6];
    const float* bih0r = (const float*)d_in[7];
    const float* bhh0r = (const float*)d_in[8];
    const float* Wih1  = (const float*)d_in[9];
    const float* Whh1  = (const float*)d_in[10];
    const float* bih1  = (const float*)d_in[11];
    const float* bhh1  = (const float*)d_in[12];
    const float* Wih1r = (const float*)d_in[13];
    const float* Whh1r = (const float*)d_in[14];
    const float* bih1r = (const float*)d_in[15];
    const float* bhh1r = (const float*)d_in[16];
    const float* fc1w  = (const float*)d_in[17];
    const float* fc1b  = (const float*)d_in[18];
    const float* fc2w  = (const float*)d_in[19];
    const float* fc2b  = (const float*)d_in[20];
    float* out = (float*)d_out;

    const int SMEMR = (WWORDS + 2 * HSW) * 4;   // 229,632 B <= 232,448 cap
    cudaFuncSetAttribute(lstm_rec, cudaFuncAttributeMaxDynamicSharedMemorySize, SMEMR);

    dim3 gg(Bb * Tt / 128, GH / 128, 2);
    dim3 gr(Bb / NB, 2);

    // layer 0
    xg_gemm<<<gg, 256>>>(x, 0, Ii, Wih0, Wih0r, bih0, bhh0, bih0r, bhh0r);
    lstm_rec<<<gr, 512, SMEMR>>>(0, Whh0, Whh0r);
    // layer 1 (input = g_h0, K = 256)
    xg_gemm<<<gg, 256>>>(x, 1, 2 * Hh, Wih1, Wih1r, bih1, bhh1, bih1r, bhh1r);
    lstm_rec<<<gr, 512, SMEMR>>>(1, Whh1, Whh1r);
    // head
    fc_head<<<Bb, Hh>>>(fc1w, fc1b, fc2w, fc2b, out);
}